// round 11
// baseline (speedup 1.0000x reference)
#include <cuda_runtime.h>
#include <cuda_bf16.h>
#include <math.h>
#include <stdint.h>

// ---- model constants ----
#define Bq   32
#define IMGS 128
#define Dm   512
#define NH   8
#define NL   8
#define MLPD 2048
#define NP   256
#define NT   257
#define HDm  64

// ---- scratch (device globals; no allocation allowed) ----
__device__ float g_comb[Bq * NP * 2 * Dm];           // fp32 for gate-fuse epilogue
__device__ float g_tok [Bq * NT * Dm];
__device__ float g_qkv [Bq * NT * 3 * Dm];
// split-packed bf16 activation operands (hi/lo word arrays)
__device__ uint32_t g_combh[Bq * NP * 512];
__device__ uint32_t g_combl[Bq * NP * 512];
__device__ uint32_t g_xh[Bq * NT * 256];
__device__ uint32_t g_xl[Bq * NT * 256];
__device__ uint32_t g_oh[Bq * NT * 256];
__device__ uint32_t g_ol[Bq * NT * 256];
__device__ uint32_t g_hh[Bq * NT * 1024];
__device__ uint32_t g_hl[Bq * NT * 1024];
// transposed weights, bf16-split, packed: [N][K/2]
#define WT_ELEMS (512*1024 + NL * (1536*512 + 512*512 + 2048*512 + 512*2048))
__device__ uint32_t g_wTh[WT_ELEMS / 2];
__device__ uint32_t g_wTl[WT_ELEMS / 2];

#define FWT_OFFW    0
#define LAYER_OFFW(l) (262144 + (size_t)(l) * 1572864)
#define QKVT_OFFW   0
#define PROJT_OFFW  393216
#define W1T_OFFW    524288
#define W2T_OFFW    1048576

__device__ __forceinline__ void bf16_split_pack(float v0, float v1,
                                                uint32_t& hw, uint32_t& lw) {
    __nv_bfloat16 h0 = __float2bfloat16(v0), h1 = __float2bfloat16(v1);
    float r0 = v0 - __bfloat162float(h0);
    float r1 = v1 - __bfloat162float(h1);
    __nv_bfloat16 l0 = __float2bfloat16(r0), l1 = __float2bfloat16(r1);
    hw = (uint32_t)__bfloat16_as_ushort(h0) | ((uint32_t)__bfloat16_as_ushort(h1) << 16);
    lw = (uint32_t)__bfloat16_as_ushort(l0) | ((uint32_t)__bfloat16_as_ushort(l1) << 16);
}

__device__ __forceinline__ void mma16(float c[4], const uint32_t a[4], const uint32_t b[2]) {
    asm volatile(
        "mma.sync.aligned.m16n8k16.row.col.f32.bf16.bf16.f32 "
        "{%0,%1,%2,%3}, {%4,%5,%6,%7}, {%8,%9}, {%0,%1,%2,%3};"
        : "+f"(c[0]), "+f"(c[1]), "+f"(c[2]), "+f"(c[3])
        : "r"(a[0]), "r"(a[1]), "r"(a[2]), "r"(a[3]), "r"(b[0]), "r"(b[1]));
}

__device__ __forceinline__ void cp16(uint32_t dst, const void* src) {
    asm volatile("cp.async.cg.shared.global [%0], [%1], 16;" :: "r"(dst), "l"(src));
}

// GEMM tile 64x128, 128 threads (4 warps), 4-stage pipeline.
// smem per stage (words): Ah 64*12=768, Al 768, Bh 128*12=1536, Bl 1536 -> 4608
#define AS_W 12
#define A_ARR_W 768
#define B_ARR_W 1536
#define STAGE_W 4608
#define NSTAGE 4
#define GEMM_SMEM_BYTES (NSTAGE * STAGE_W * 4)   // 73728 B -> 3 CTAs/SM

// ============================================================
// bf16-split GEMM, 64x128 tile, 128 thr, 4 warps (2M x 2N),
// warp tile 32x64, 3 x mma.m16n8k16 per (mf,nf).
// act: 0 none, 1 sigmoid, 2 gelu, 3 gate-fuse.
// Requires N%128==0, K%16==0, K/16 >= NSTAGE.
// ============================================================
__global__ __launch_bounds__(128, 3) void mma_gemm(
    const uint32_t* __restrict__ Ah, const uint32_t* __restrict__ Al,
    const uint32_t* __restrict__ BTh, const uint32_t* __restrict__ BTl,
    const float* __restrict__ bias, const float* __restrict__ res,
    float* __restrict__ C, uint32_t* __restrict__ Ch, uint32_t* __restrict__ Cl,
    const float* __restrict__ comb, const float* __restrict__ pos,
    float* __restrict__ tokout,
    int M, int N, int K, int act)
{
    extern __shared__ uint32_t smu[];
    int tid = threadIdx.x;
    int wid = tid >> 5, lane = tid & 31;
    int g = lane >> 2, tig = lane & 3;
    int m0 = blockIdx.y * 64, n0 = blockIdx.x * 128;
    int wmi = wid & 1, wni = wid >> 1;
    int Kw = K >> 1;

    // load coords: A rows 0..63 (2 thr/row), B rows 0..127 (2 rows/thr)
    int lr = tid >> 1, lw4 = (tid & 1) * 4;
    int gma = m0 + lr; if (gma > M - 1) gma = M - 1;
    size_t aoff  = (size_t)gma * Kw + lw4;
    size_t boff0 = (size_t)(n0 + lr) * Kw + lw4;
    size_t boff1 = (size_t)(n0 + lr + 64) * Kw + lw4;
    uint32_t sbase = (uint32_t)__cvta_generic_to_shared(smu);
    uint32_t sA  = sbase + (uint32_t)(lr * AS_W + lw4) * 4;
    uint32_t sB0 = sbase + (uint32_t)(2 * A_ARR_W + lr * AS_W + lw4) * 4;
    uint32_t sB1 = sB0 + (uint32_t)(64 * AS_W) * 4;

    float c[2][8][4] = {};
    int ntiles = K >> 4;

#define ISSUE(T) do {                                                          \
        uint32_t stoff = ((T) & (NSTAGE - 1)) * (STAGE_W * 4);                 \
        size_t ko = (size_t)(T) * 8;                                           \
        cp16(sA  + stoff,                    Ah  + aoff  + ko);                \
        cp16(sA  + stoff + A_ARR_W * 4,      Al  + aoff  + ko);                \
        cp16(sB0 + stoff,                    BTh + boff0 + ko);                \
        cp16(sB1 + stoff,                    BTh + boff1 + ko);                \
        cp16(sB0 + stoff + B_ARR_W * 4,      BTl + boff0 + ko);                \
        cp16(sB1 + stoff + B_ARR_W * 4,      BTl + boff1 + ko);                \
        asm volatile("cp.async.commit_group;" ::: "memory");                   \
    } while (0)

    #pragma unroll
    for (int s = 0; s < NSTAGE - 1; s++) ISSUE(s);

    for (int t = 0; t < ntiles; t++) {
        int rem = ntiles - 1 - t;
        if (rem >= 2)      asm volatile("cp.async.wait_group 2;" ::: "memory");
        else if (rem == 1) asm volatile("cp.async.wait_group 1;" ::: "memory");
        else               asm volatile("cp.async.wait_group 0;" ::: "memory");
        __syncthreads();

        if (t + NSTAGE - 1 < ntiles) ISSUE(t + NSTAGE - 1);

        const uint32_t* bufp = smu + (t & (NSTAGE - 1)) * STAGE_W;
        const uint32_t* AhS = bufp;
        const uint32_t* AlS = bufp + A_ARR_W;
        const uint32_t* BhS = bufp + 2 * A_ARR_W;
        const uint32_t* BlS = bufp + 2 * A_ARR_W + B_ARR_W;

        uint32_t afh[2][4], afl[2][4];
        #pragma unroll
        for (int mf = 0; mf < 2; mf++) {
            int r1 = (wmi * 32 + mf * 16 + g) * AS_W;
            int r2 = r1 + 8 * AS_W;
            afh[mf][0] = AhS[r1 + tig];     afh[mf][1] = AhS[r2 + tig];
            afh[mf][2] = AhS[r1 + tig + 4]; afh[mf][3] = AhS[r2 + tig + 4];
            afl[mf][0] = AlS[r1 + tig];     afl[mf][1] = AlS[r2 + tig];
            afl[mf][2] = AlS[r1 + tig + 4]; afl[mf][3] = AlS[r2 + tig + 4];
        }
        #pragma unroll
        for (int nf = 0; nf < 8; nf++) {
            int rb = (wni * 64 + nf * 8 + g) * AS_W;
            uint32_t bh2[2] = {BhS[rb + tig], BhS[rb + tig + 4]};
            uint32_t bl2[2] = {BlS[rb + tig], BlS[rb + tig + 4]};
            #pragma unroll
            for (int mf = 0; mf < 2; mf++) {
                mma16(c[mf][nf], afh[mf], bl2);
                mma16(c[mf][nf], afl[mf], bh2);
                mma16(c[mf][nf], afh[mf], bh2);
            }
        }
    }
#undef ISSUE

    // ---- epilogue ----
    int wm = wmi * 32, wn = wni * 64;
    int Nw = N >> 1;
    #pragma unroll
    for (int mf = 0; mf < 2; mf++) {
        #pragma unroll
        for (int rh = 0; rh < 2; rh++) {
            int m = m0 + wm + mf * 16 + g + rh * 8;
            if (m >= M) continue;
            #pragma unroll
            for (int nf = 0; nf < 8; nf++) {
                int n = n0 + wn + nf * 8 + 2 * tig;
                float vx = c[mf][nf][rh * 2], vy = c[mf][nf][rh * 2 + 1];
                if (bias) {
                    float2 bb = *(const float2*)&bias[n];
                    vx += bb.x; vy += bb.y;
                }
                if (act == 1) {
                    vx = 1.f / (1.f + expf(-vx));
                    vy = 1.f / (1.f + expf(-vy));
                } else if (act == 2) {
                    vx = 0.5f * vx * (1.f + erff(vx * 0.70710678118654752f));
                    vy = 0.5f * vy * (1.f + erff(vy * 0.70710678118654752f));
                } else if (act == 3) {
                    float gx = 1.f / (1.f + expf(-vx));
                    float gy = 1.f / (1.f + expf(-vy));
                    size_t mr = (size_t)m * 1024;
                    float2 sv = *(const float2*)&comb[mr + n];
                    float2 ov = *(const float2*)&comb[mr + 512 + n];
                    int p = m & 255, b = m >> 8;
                    float2 pp = *(const float2*)&pos[(size_t)(1 + p) * Dm + n];
                    float ox = gx * sv.x + (1.f - gx) * ov.x + pp.x;
                    float oy = gy * sv.y + (1.f - gy) * ov.y + pp.y;
                    *(float2*)&tokout[((size_t)(b * NT + 1 + p)) * Dm + n] = make_float2(ox, oy);
                    continue;
                }
                if (res) {
                    float2 rr = *(const float2*)&res[(size_t)m * N + n];
                    vx += rr.x; vy += rr.y;
                }
                if (C) *(float2*)&C[(size_t)m * N + n] = make_float2(vx, vy);
                if (Ch) {
                    uint32_t hw_, lw_;
                    bf16_split_pack(vx, vy, hw_, lw_);
                    size_t o = (size_t)m * Nw + (n >> 1);
                    Ch[o] = hw_; Cl[o] = lw_;
                }
            }
        }
    }
}

// ============================================================
// ALL weight transposes in ONE launch
// ============================================================
__global__ void transpose_all(const float* __restrict__ fw,
                              const float* __restrict__ qkvw,
                              const float* __restrict__ projw,
                              const float* __restrict__ w1,
                              const float* __restrict__ w2,
                              uint32_t* __restrict__ dsth,
                              uint32_t* __restrict__ dstl)
{
    int id = blockIdx.x;
    const float* src; int K, N; size_t base; int loc;
    if (id < 512) { src = fw; K = 1024; N = 512; base = 0; loc = id; }
    else {
        int t = id - 512, l = t / 3072, r = t % 3072;
        size_t L = LAYER_OFFW(l);
        if (r < 768)       { src = qkvw  + (size_t)l * 786432;  K = 512;  N = 1536; base = L;               loc = r; }
        else if (r < 1024) { src = projw + (size_t)l * 262144;  K = 512;  N = 512;  base = L + PROJT_OFFW;  loc = r - 768; }
        else if (r < 2048) { src = w1    + (size_t)l * 1048576; K = 512;  N = 2048; base = L + W1T_OFFW;    loc = r - 1024; }
        else               { src = w2    + (size_t)l * 1048576; K = 2048; N = 512;  base = L + W2T_OFFW;    loc = r - 2048; }
    }
    int ntx = N >> 5;
    int kb = (loc / ntx) << 5, nb = (loc % ntx) << 5;

    __shared__ float t[32][33];
    int tx = threadIdx.x & 31, ty = threadIdx.x >> 5;
    #pragma unroll
    for (int j = 0; j < 32; j += 8)
        t[ty + j][tx] = src[(size_t)(kb + ty + j) * N + nb + tx];
    __syncthreads();

    int w = threadIdx.x & 15, r2 = threadIdx.x >> 4;
    int Kw = K >> 1;
    #pragma unroll
    for (int j = 0; j < 32; j += 16) {
        int row = r2 + j;
        float v0 = t[2 * w][row], v1 = t[2 * w + 1][row];
        uint32_t hw_, lw_; bf16_split_pack(v0, v1, hw_, lw_);
        size_t o = base + (size_t)(nb + row) * Kw + (kb >> 1) + w;
        dsth[o] = hw_; dstl[o] = lw_;
    }
}

// ============================================================
// SPT: conv + LN, writes fp32 comb AND split-packed comb
// ============================================================
__device__ __forceinline__ float ln512(float a, float* red, int tid) {
    red[tid] = a; __syncthreads();
    for (int s = 256; s > 0; s >>= 1) { if (tid < s) red[tid] += red[tid + s]; __syncthreads(); }
    float mu = red[0] * (1.f / 512.f); __syncthreads();
    float dv = a - mu;
    red[tid] = dv * dv; __syncthreads();
    for (int s = 256; s > 0; s >>= 1) { if (tid < s) red[tid] += red[tid + s]; __syncthreads(); }
    float var = red[0] * (1.f / 512.f); __syncthreads();
    return dv * rsqrtf(var + 1e-5f);
}

__global__ void spt_kernel(const float* __restrict__ img,
    const float* __restrict__ w0, const float* __restrict__ bb0,
    const float* __restrict__ gg0, const float* __restrict__ be0,
    const float* __restrict__ w1, const float* __restrict__ bb1,
    const float* __restrict__ gg1, const float* __restrict__ be1,
    float* __restrict__ comb, uint32_t* __restrict__ combh, uint32_t* __restrict__ combl)
{
    int blk = blockIdx.x;
    int b = blk >> 8;
    int p = blk & 255;
    int py = p >> 4, px = p & 15;

    __shared__ float patch[10][10];
    __shared__ float red[512];
    int tid = threadIdx.x;

    if (tid < 100) {
        int r = tid / 10, c = tid % 10;
        int ir = (py * 8 - 1 + r) & 127;
        int ic = (px * 8 - 1 + c) & 127;
        patch[r][c] = img[((size_t)b * IMGS + ir) * IMGS + ic];
    }
    __syncthreads();

    const int dy[5] = {1, 0, 2, 0, 2};
    const int dx[5] = {1, 0, 0, 2, 2};

    int d = tid;
    float a0 = bb0[d], a1 = bb1[d];
    const float* wp0 = w0 + (size_t)d * 320;
    const float* wp1 = w1 + (size_t)d * 320;

    for (int c = 0; c < 5; c++) {
        #pragma unroll
        for (int i = 0; i < 8; i++) {
            #pragma unroll
            for (int j = 0; j < 8; j++) {
                float xv = patch[i + dy[c]][j + dx[c]];
                int wi = (c * 8 + i) * 8 + j;
                a0 = fmaf(wp0[wi], xv, a0);
                a1 = fmaf(wp1[wi], xv, a1);
            }
        }
    }

    float n0 = ln512(a0, red, tid) * gg0[d] + be0[d];
    float n1 = ln512(a1, red, tid) * gg1[d] + be1[d];

    size_t row = blk;
    comb[row * 1024 + d]       = n0;
    comb[row * 1024 + 512 + d] = n1;

    red[tid] = n0; __syncthreads();
    if (tid < 256) {
        uint32_t h, l; bf16_split_pack(red[2 * tid], red[2 * tid + 1], h, l);
        combh[row * 512 + tid] = h; combl[row * 512 + tid] = l;
    }
    __syncthreads();
    red[tid] = n1; __syncthreads();
    if (tid < 256) {
        uint32_t h, l; bf16_split_pack(red[2 * tid], red[2 * tid + 1], h, l);
        combh[row * 512 + 256 + tid] = h; combl[row * 512 + 256 + tid] = l;
    }
}

// ============================================================
// LayerNorm over D=512 -> split-packed output
// ============================================================
__global__ void ln_kernel(const float* __restrict__ in, const float* __restrict__ g,
                          const float* __restrict__ bta,
                          uint32_t* __restrict__ xh, uint32_t* __restrict__ xl)
{
    int row = blockIdx.x, tid = threadIdx.x;   // 128
    __shared__ float red[128];
    float4 v = *(const float4*)&in[(size_t)row * Dm + tid * 4];
    red[tid] = v.x + v.y + v.z + v.w; __syncthreads();
    for (int st = 64; st > 0; st >>= 1) { if (tid < st) red[tid] += red[tid + st]; __syncthreads(); }
    float mu = red[0] * (1.f / 512.f); __syncthreads();
    float dx = v.x - mu, dyv = v.y - mu, dz = v.z - mu, dw = v.w - mu;
    red[tid] = dx * dx + dyv * dyv + dz * dz + dw * dw; __syncthreads();
    for (int st = 64; st > 0; st >>= 1) { if (tid < st) red[tid] += red[tid + st]; __syncthreads(); }
    float inv = rsqrtf(red[0] * (1.f / 512.f) + 1e-5f);
    float4 gg = *(const float4*)&g[tid * 4];
    float4 bb = *(const float4*)&bta[tid * 4];
    float y0 = dx  * inv * gg.x + bb.x;
    float y1 = dyv * inv * gg.y + bb.y;
    float y2 = dz  * inv * gg.z + bb.z;
    float y3 = dw  * inv * gg.w + bb.w;
    uint32_t h0, l0, h1, l1;
    bf16_split_pack(y0, y1, h0, l0);
    bf16_split_pack(y2, y3, h1, l1);
    size_t o = (size_t)row * 256 + tid * 2;
    xh[o] = h0; xh[o + 1] = h1;
    xl[o] = l0; xl[o + 1] = l1;
}

// ============================================================
// Tiled fused attention -> split-packed o
// ============================================================
#define QTILES 5
#define SS_LD  260
#define ATTN_SMEM ((64*68 + 64*68 + 64*SS_LD) * 4)

__global__ __launch_bounds__(256) void attn_kernel(
    const float* __restrict__ qkv, const float* __restrict__ temp,
    uint32_t* __restrict__ oh, uint32_t* __restrict__ ol)
{
    extern __shared__ float smf[];
    float* Qs  = smf;
    float* KVs = smf + 64 * 68;
    float* Ss  = smf + 2 * 64 * 68;

    int qt = blockIdx.x, h = blockIdx.y, b = blockIdx.z;
    int tid = threadIdx.x;
    int tx = tid & 15, ty = tid >> 4;

    const size_t base = (size_t)b * NT * 1536 + (size_t)h * 64;

    {
        int dth = (tid & 15) * 4;
        #pragma unroll
        for (int pass = 0; pass < 4; pass++) {
            int q = (tid >> 4) + pass * 16;
            int n = qt * 64 + q; if (n > NT - 1) n = NT - 1;
            float4 v = *(const float4*)&qkv[base + (size_t)n * 1536 + dth];
            Qs[(dth + 0) * 68 + q] = v.x;
            Qs[(dth + 1) * 68 + q] = v.y;
            Qs[(dth + 2) * 68 + q] = v.z;
            Qs[(dth + 3) * 68 + q] = v.w;
        }
    }

    float tmp = temp[h];
    int nbase = qt * 64;

    for (int mc = 0; mc < NT; mc += 64) {
        __syncthreads();
        {
            int dth = (tid & 15) * 4;
            #pragma unroll
            for (int pass = 0; pass < 4; pass++) {
                int m = (tid >> 4) + pass * 16;
                int mg = mc + m; if (mg > NT - 1) mg = NT - 1;
                float4 v = *(const float4*)&qkv[base + 512 + (size_t)mg * 1536 + dth];
                KVs[(dth + 0) * 68 + m] = v.x;
                KVs[(dth + 1) * 68 + m] = v.y;
                KVs[(dth + 2) * 68 + m] = v.z;
                KVs[(dth + 3) * 68 + m] = v.w;
            }
        }
        __syncthreads();

        float acc[4][4] = {};
        #pragma unroll
        for (int kk = 0; kk < 64; kk++) {
            float4 a = *(const float4*)&Qs[kk * 68 + ty * 4];
            float4 bb = *(const float4*)&KVs[kk * 68 + tx * 4];
            float av[4] = {a.x, a.y, a.z, a.w};
            float bv[4] = {bb.x, bb.y, bb.z, bb.w};
            #pragma unroll
            for (int i = 0; i < 4; i++)
                #pragma unroll
                for (int j = 0; j < 4; j++)
                    acc[i][j] = fmaf(av[i], bv[j], acc[i][j]);
        }
        #pragma unroll
        for (int i = 0; i < 4; i++) {
            int q = ty * 4 + i;
            int n = nbase + q;
            #pragma unroll
            for (int j = 0; j < 4; j++) {
                int m = mc + tx * 4 + j;
                if (m < NT) {
                    float s = acc[i][j] * tmp;
                    if (m == n) s = -INFINITY;
                    Ss[q * SS_LD + m] = s;
                }
            }
        }
    }
    __syncthreads();

    {
        int wid = tid >> 5, lane = tid & 31;
        for (int r = 0; r < 8; r++) {
            float* row = Ss + (wid * 8 + r) * SS_LD;
            float mx = -INFINITY;
            for (int m = lane; m < NT; m += 32) mx = fmaxf(mx, row[m]);
            #pragma unroll
            for (int s = 16; s > 0; s >>= 1) mx = fmaxf(mx, __shfl_xor_sync(0xffffffffu, mx, s));
            float sum = 0.f;
            for (int m = lane; m < NT; m += 32) { float e = expf(row[m] - mx); row[m] = e; sum += e; }
            #pragma unroll
            for (int s = 16; s > 0; s >>= 1) sum += __shfl_xor_sync(0xffffffffu, sum, s);
            float inv = 1.f / sum;
            for (int m = lane; m < NT; m += 32) row[m] *= inv;
        }
    }

    float acc[4][4] = {};
    for (int mc = 0; mc < NT; mc += 64) {
        __syncthreads();
        {
            int dth = (tid & 15) * 4;
            #pragma unroll
            for (int pass = 0; pass < 4; pass++) {
                int m = (tid >> 4) + pass * 16;
                int mg = mc + m; if (mg > NT - 1) mg = NT - 1;
                float4 v = *(const float4*)&qkv[base + 1024 + (size_t)mg * 1536 + dth];
                *(float4*)&KVs[m * 68 + dth] = v;
            }
        }
        __syncthreads();
        int mlim = NT - mc; if (mlim > 64) mlim = 64;
        for (int mm = 0; mm < mlim; mm++) {
            float4 bb = *(const float4*)&KVs[mm * 68 + tx * 4];
            float bv[4] = {bb.x, bb.y, bb.z, bb.w};
            #pragma unroll
            for (int i = 0; i < 4; i++) {
                float p = Ss[(ty * 4 + i) * SS_LD + mc + mm];
                #pragma unroll
                for (int j = 0; j < 4; j++)
                    acc[i][j] = fmaf(p, bv[j], acc[i][j]);
            }
        }
    }

    #pragma unroll
    for (int i = 0; i < 4; i++) {
        int n = nbase + ty * 4 + i;
        if (n < NT) {
            uint32_t h0, l0, h1, l1;
            bf16_split_pack(acc[i][0], acc[i][1], h0, l0);
            bf16_split_pack(acc[i][2], acc[i][3], h1, l1);
            size_t o = (size_t)(b * NT + n) * 256 + h * 32 + tx * 2;
            oh[o] = h0; oh[o + 1] = h1;
            ol[o] = l0; ol[o + 1] = l1;
        }
    }
}

// ============================================================
// cls row init
// ============================================================
__global__ void cls_kernel(const float* __restrict__ cls, const float* __restrict__ pos,
                           float* __restrict__ tok)
{
    int idx = blockIdx.x * blockDim.x + threadIdx.x;
    if (idx >= Bq * Dm) return;
    int d = idx & 511, b = idx >> 9;
    tok[(size_t)b * NT * Dm + d] = cls[d] + pos[d];
}

// ============================================================
// Head
// ============================================================
__global__ void head_kernel(const float* __restrict__ tok, const float* __restrict__ ng,
                            const float* __restrict__ nb, const float* __restrict__ hw,
                            const float* __restrict__ hb, float* __restrict__ out)
{
    int b = blockIdx.x, tid = threadIdx.x;
    __shared__ float red[128];
    const float* xr = tok + (size_t)b * NT * Dm;
    float v[4]; float s = 0.f;
    #pragma unroll
    for (int i = 0; i < 4; i++) { v[i] = xr[tid + 128 * i]; s += v[i]; }
    red[tid] = s; __syncthreads();
    for (int st = 64; st > 0; st >>= 1) { if (tid < st) red[tid] += red[tid + st]; __syncthreads(); }
    float mu = red[0] * (1.f / 512.f); __syncthreads();
    float s2 = 0.f;
    #pragma unroll
    for (int i = 0; i < 4; i++) { float dv = v[i] - mu; s2 += dv * dv; }
    red[tid] = s2; __syncthreads();
    for (int st = 64; st > 0; st >>= 1) { if (tid < st) red[tid] += red[tid + st]; __syncthreads(); }
    float inv = rsqrtf(red[0] * (1.f / 512.f) + 1e-5f);
    __syncthreads();

    float xn[4];
    #pragma unroll
    for (int i = 0; i < 4; i++) {
        int idx = tid + 128 * i;
        xn[i] = (v[i] - mu) * inv * ng[idx] + nb[idx];
    }

    for (int c = 0; c < 3; c++) {
        float p = 0.f;
        #pragma unroll
        for (int i = 0; i < 4; i++) {
            int idx = tid + 128 * i;
            p = fmaf(xn[i], hw[idx * 3 + c], p);
        }
        red[tid] = p; __syncthreads();
        for (int st = 64; st > 0; st >>= 1) { if (tid < st) red[tid] += red[tid + st]; __syncthreads(); }
        if (tid == 0) out[b * 3 + c] = red[0] + hb[c];
        __syncthreads();
    }
}

// ============================================================
// Launch
// ============================================================
static uint32_t* s_wTh = nullptr;
static uint32_t* s_wTl = nullptr;

static inline void launch_gemm(const uint32_t* Ah, const uint32_t* Al, size_t wOffW,
                               const float* bias, const float* res,
                               float* C, uint32_t* Ch, uint32_t* Cl,
                               const float* comb, const float* pos, float* tokout,
                               int M, int Nn, int K, int act)
{
    dim3 grid(Nn / 128, (M + 63) / 64);
    mma_gemm<<<grid, 128, GEMM_SMEM_BYTES>>>(Ah, Al, s_wTh + wOffW, s_wTl + wOffW,
                                             bias, res, C, Ch, Cl, comb, pos, tokout,
                                             M, Nn, K, act);
}

extern "C" void kernel_launch(void* const* d_in, const int* in_sizes, int n_in,
                              void* d_out, int out_size)
{
    const float* image   = (const float*)d_in[0];
    const float* ssw     = (const float*)d_in[1];
    const float* ssb     = (const float*)d_in[2];
    const float* ssg     = (const float*)d_in[3];
    const float* ssbeta  = (const float*)d_in[4];
    const float* sow     = (const float*)d_in[5];
    const float* sob     = (const float*)d_in[6];
    const float* sog     = (const float*)d_in[7];
    const float* sobeta  = (const float*)d_in[8];
    const float* fw      = (const float*)d_in[9];
    const float* fb      = (const float*)d_in[10];
    const float* cls     = (const float*)d_in[11];
    const float* pos     = (const float*)d_in[12];
    const float* ln1g    = (const float*)d_in[13];
    const float* ln1b    = (const float*)d_in[14];
    const float* qkvw    = (const float*)d_in[15];
    const float* qkvb    = (const float*)d_in[16];
    const float* projw   = (const float*)d_in[17];
    const float* projb   = (const float*)d_in[18];
    const float* temp    = (const float*)d_in[19];
    const float* ln2g    = (const float*)d_in[20];
    const float* ln2b    = (const float*)d_in[21];
    const float* w1      = (const float*)d_in[22];
    const float* b1      = (const float*)d_in[23];
    const float* w2      = (const float*)d_in[24];
    const float* b2      = (const float*)d_in[25];
    const float* ng      = (const float*)d_in[26];
    const float* nb      = (const float*)d_in[27];
    const float* hw      = (const float*)d_in[28];
    const float* hb      = (const float*)d_in[29];

    float *comb, *tok, *qkv;
    uint32_t *combh, *combl, *xh, *xl, *oh, *ol, *hh, *hl;
    cudaGetSymbolAddress((void**)&comb,  g_comb);
    cudaGetSymbolAddress((void**)&tok,   g_tok);
    cudaGetSymbolAddress((void**)&qkv,   g_qkv);
    cudaGetSymbolAddress((void**)&combh, g_combh);
    cudaGetSymbolAddress((void**)&combl, g_combl);
    cudaGetSymbolAddress((void**)&xh,    g_xh);
    cudaGetSymbolAddress((void**)&xl,    g_xl);
    cudaGetSymbolAddress((void**)&oh,    g_oh);
    cudaGetSymbolAddress((void**)&ol,    g_ol);
    cudaGetSymbolAddress((void**)&hh,    g_hh);
    cudaGetSymbolAddress((void**)&hl,    g_hl);
    cudaGetSymbolAddress((void**)&s_wTh, g_wTh);
    cudaGetSymbolAddress((void**)&s_wTl, g_wTl);

    cudaFuncSetAttribute(mma_gemm, cudaFuncAttributeMaxDynamicSharedMemorySize, GEMM_SMEM_BYTES);
    cudaFuncSetAttribute(attn_kernel, cudaFuncAttributeMaxDynamicSharedMemorySize, ATTN_SMEM);

    const int Mtok = Bq * NT;   // 8224
    const int Mpat = Bq * NP;   // 8192

    // launch 0: cls init (tiny)
    cls_kernel<<<(Bq * Dm + 255) / 256, 256>>>(cls, pos, tok);
    // launch 1: weight transposes
    transpose_all<<<25088, 256>>>(fw, qkvw, projw, w1, w2, s_wTh, s_wTl);
    // launch 2: SPT
    spt_kernel<<<Mpat, 512>>>(image, ssw, ssb, ssg, ssbeta,
                              sow, sob, sog, sobeta, comb, combh, combl);
    // launch 3: gate GEMM with fused token-mix epilogue  <-- profiled slot
    launch_gemm(combh, combl, FWT_OFFW, fb, nullptr, nullptr, nullptr, nullptr,
                comb, pos, tok, Mpat, Dm, 2 * Dm, /*gate-fuse*/3);

    for (int l = 0; l < NL; l++) {
        size_t lb = LAYER_OFFW(l);
        ln_kernel<<<Mtok, 128>>>(tok, ln1g + l * Dm, ln1b + l * Dm, xh, xl);
        launch_gemm(xh, xl, lb + QKVT_OFFW, qkvb + l * 3 * Dm, nullptr,
                    qkv, nullptr, nullptr, nullptr, nullptr, nullptr, Mtok, 3 * Dm, Dm, 0);
        attn_kernel<<<dim3(QTILES, NH, Bq), 256, ATTN_SMEM>>>(qkv, temp + l * NH, oh, ol);
        launch_gemm(oh, ol, lb + PROJT_OFFW, projb + l * Dm, tok,
                    tok, nullptr, nullptr, nullptr, nullptr, nullptr, Mtok, Dm, Dm, 0);
        ln_kernel<<<Mtok, 128>>>(tok, ln2g + l * Dm, ln2b + l * Dm, xh, xl);
        launch_gemm(xh, xl, lb + W1T_OFFW, b1 + l * MLPD, nullptr,
                    nullptr, hh, hl, nullptr, nullptr, nullptr, Mtok, MLPD, Dm, /*gelu*/2);
        launch_gemm(hh, hl, lb + W2T_OFFW, b2 + l * Dm, tok,
                    tok, nullptr, nullptr, nullptr, nullptr, nullptr, Mtok, Dm, MLPD, 0);
    }

    head_kernel<<<Bq, 128>>>(tok, ng, nb, hw, hb, (float*)d_out);
}